// round 16
// baseline (speedup 1.0000x reference)
#include <cuda_runtime.h>
#include <cuda_bf16.h>
#include <mma.h>
#include <math.h>
#include <stdint.h>

using namespace nvcuda;

#define BB 16
#define LL 2048
#define WIN 128
#define DD 512
#define HH 8
#define HD 64
#define FF 2048
#define NLAYER 3
#define VV 32000
#define MMOT 32
#define SS 129            // WIN + 1 (cond row)
#define RT (BB*SS)        // 2064 transformer rows
#define RTP 2176          // RT padded to 128
#define WR (BB*WIN)       // 2048 window rows
#define EPSV 1e-5f
#define NCH2 (VV/128)     // 250 softmax partial chunks

#define TROW 72                    // padded tile row stride (elems)
#define TILE_ELEMS (128*TROW)      // 9216
#define STG (64*TROW*2 + 128*TROW*2)   // 27648 bytes per stage (A64 + B128)
#define DYNSM (4*STG + 32)
#define SCPAD 16644                // SS*SS=16641 padded to mult of 4 (16B align for kv)
#define ATTSMEM ((SCPAD + SS*HD)*4)    // 99600 bytes

// ---------------- mbarrier / bulk-copy PTX macros ----------------------------
#define MBARRIER_INIT(mbar_smem_addr, count) \
    asm volatile("mbarrier.init.shared.b64 [%0], %1;" \
        :: "r"((uint32_t)(mbar_smem_addr)), "r"((uint32_t)(count)) : "memory")

#define MBARRIER_EXPECT_TX(mbar_smem_addr, tx_bytes) \
    asm volatile("mbarrier.arrive.expect_tx.shared.b64 _, [%0], %1;" \
        :: "r"((uint32_t)(mbar_smem_addr)), "r"((uint32_t)(tx_bytes)) : "memory")

#define MBARRIER_WAIT_PARITY(mbar_smem_addr, phase_parity) do { \
    uint32_t _mbar = (uint32_t)(mbar_smem_addr); \
    uint32_t _parity = (uint32_t)(phase_parity); \
    uint32_t _done; \
    asm volatile( \
        "{\n\t" \
        ".reg .pred p;\n\t" \
        "mbarrier.try_wait.parity.acquire.cta.shared::cta.b64 p, [%1], %2;\n\t" \
        "selp.b32 %0, 1, 0, p;\n\t" \
        "}" \
        : "=r"(_done) : "r"(_mbar), "r"(_parity) : "memory"); \
    if (!_done) { \
        asm volatile( \
            "{\n\t" \
            ".reg .pred P1;\n\t" \
            "WAIT_LOOP_%=:\n\t" \
            "mbarrier.try_wait.parity.acquire.cta.shared::cta.b64 P1, [%0], %1, 0x989680;\n\t" \
            "@P1 bra.uni WAIT_DONE_%=;\n\t" \
            "bra.uni WAIT_LOOP_%=;\n\t" \
            "WAIT_DONE_%=:\n\t" \
            "}" \
            :: "r"(_mbar), "r"(_parity) : "memory"); \
    } \
} while(0)

#define BULK_LOAD(dst_smem, src_gmem, nbytes, mbar_smem) \
    asm volatile("cp.async.bulk.shared::cluster.global.mbarrier::complete_tx::bytes [%0], [%1], %2, [%3];" \
        :: "r"((uint32_t)(dst_smem)), "l"(src_gmem), "r"((uint32_t)(nbytes)), \
           "r"((uint32_t)(mbar_smem)) : "memory")

#define FENCE_PROXY_ASYNC() \
    asm volatile("fence.proxy.async.shared::cta;" ::: "memory")

__device__ __forceinline__ uint32_t sptr(const void* p) {
    return (uint32_t)__cvta_generic_to_shared(p);
}

// packed layout offset: tiles [m/128][k/64] of [128][TROW]
__device__ __forceinline__ size_t pk(int m, int k, int KC) {
    return ((size_t)(m >> 7)*KC + (k >> 6))*TILE_ELEMS + (size_t)(m & 127)*TROW + (k & 63);
}

// ------------------- device scratch (static, no allocation) -------------------
__device__ float g_condin[BB*4*DD];
__device__ float g_poolpart[BB*8*3*DD];
__device__ float g_tin[BB*DD];
__device__ float g_temb[BB*DD];
__device__ float g_condout[BB*DD];
__device__ float g_x[RT*DD];
__device__ float g_xt[WR*DD];
__device__ float g_x1[WR*DD];
__device__ float g_qkv[RT*3*DD];
__device__ float g_tmp[RT*DD];
__device__ float g_predv[RTP*DD];
__device__ float2 g_smpart[(size_t)WR*NCH2];
__device__ float g_picked[WR];
__device__ float g_rowrecon[WR];
__device__ float g_velred[256];
__device__ int g_comporig[WR];
__device__ int g_complabel[WR];
__device__ int g_amap[WR];
__device__ int g_nvalid;

// packed bf16 activations
__device__ __align__(16) __nv_bfloat16 g_xpk[17*8*TILE_ELEMS];
__device__ __align__(16) __nv_bfloat16 g_ctxpk[17*8*TILE_ELEMS];
__device__ __align__(16) __nv_bfloat16 g_ffpk[17*32*TILE_ELEMS];
__device__ __align__(16) __nv_bfloat16 g_px1pk[16*8*TILE_ELEMS];
__device__ __align__(16) __nv_bfloat16 g_habpk[16*8*TILE_ELEMS];
// packed bf16 weights
__device__ __align__(16) __nv_bfloat16 g_wqkvP[NLAYER*12*8*TILE_ELEMS];
__device__ __align__(16) __nv_bfloat16 g_waoP[NLAYER*4*8*TILE_ELEMS];
__device__ __align__(16) __nv_bfloat16 g_wf1P[NLAYER*16*8*TILE_ELEMS];
__device__ __align__(16) __nv_bfloat16 g_wf2P[NLAYER*4*32*TILE_ELEMS];
__device__ __align__(16) __nv_bfloat16 g_woutP[4*8*TILE_ELEMS];
__device__ __align__(16) __nv_bfloat16 g_wadP[4*8*TILE_ELEMS];
__device__ __align__(16) __nv_bfloat16 g_wdecP[250*8*TILE_ELEMS];

// ------------------- fused weight packing ------------------------------------
__device__ __forceinline__ void packone(const float4* __restrict__ W,
                                        __nv_bfloat16* __restrict__ dst, int idx, int K) {
    int ck = K >> 3;
    int n = idx / ck, q = idx - n*ck;
    int k = q << 3;
    int kc = k >> 6, c8 = (k >> 3) & 7;
    int KC = K >> 6;
    size_t doff = ((size_t)(n >> 7)*KC + kc)*TILE_ELEMS + (size_t)(n & 127)*TROW + c8*8;
    float4 a = W[(size_t)idx*2], b = W[(size_t)idx*2 + 1];
    __nv_bfloat162 r0 = __float22bfloat162_rn(make_float2(a.x, a.y));
    __nv_bfloat162 r1 = __float22bfloat162_rn(make_float2(a.z, a.w));
    __nv_bfloat162 r2 = __float22bfloat162_rn(make_float2(b.x, b.y));
    __nv_bfloat162 r3 = __float22bfloat162_rn(make_float2(b.z, b.w));
    uint4 v;
    v.x = *(uint32_t*)&r0; v.y = *(uint32_t*)&r1;
    v.z = *(uint32_t*)&r2; v.w = *(uint32_t*)&r3;
    ((uint4*)dst)[doff >> 3] = v;
}

__global__ void wpack_all(const float* qkvW, const float* aoW, const float* f1W,
                          const float* f2W, const float* outW, const float* adW,
                          const float* decW) {
    int idx = blockIdx.x*blockDim.x + threadIdx.x;
    if      (idx <  294912) packone((const float4*)qkvW, g_wqkvP, idx,           512);
    else if (idx <  393216) packone((const float4*)aoW,  g_waoP,  idx - 294912,  512);
    else if (idx <  786432) packone((const float4*)f1W,  g_wf1P,  idx - 393216,  512);
    else if (idx < 1179648) packone((const float4*)f2W,  g_wf2P,  idx - 786432,  2048);
    else if (idx < 1212416) packone((const float4*)outW, g_woutP, idx - 1179648, 512);
    else if (idx < 1245184) packone((const float4*)adW,  g_wadP,  idx - 1212416, 512);
    else if (idx < 3293184) packone((const float4*)decW, g_wdecP, idx - 1245184, 512);
}

// ------------------- pools -----------------------------------------------------
__global__ void pool_partial(const int* __restrict__ tok, const int* __restrict__ ws,
                             const int* __restrict__ we, const float* __restrict__ emb) {
    int b = blockIdx.x, c = blockIdx.y, d = threadIdx.x;
    int s0 = ws[b], e0 = we[b];
    float gl = 0.f, lf = 0.f, rt = 0.f;
    int l0 = c * (LL/8);
#pragma unroll 4
    for (int i = 0; i < LL/8; i++) {
        int l = l0 + i;
        int t = tok[b*LL + l];
        float v = emb[(size_t)t*DD + d];
        gl += v;
        if (l < s0)  lf += v;
        if (l >= e0) rt += v;
    }
    float* p = g_poolpart + ((size_t)(b*8 + c)*3)*DD;
    p[d] = lf; p[DD + d] = rt; p[2*DD + d] = gl;
}

__global__ void prep_kernel(const int* __restrict__ mot, const int* __restrict__ mlen,
                            const int* __restrict__ ws, const int* __restrict__ we,
                            const float* __restrict__ emb, const float* __restrict__ t) {
    int b = blockIdx.x, d = threadIdx.x;
    float lf = 0.f, rt = 0.f, gl = 0.f;
    for (int c = 0; c < 8; c++) {
        const float* p = g_poolpart + ((size_t)(b*8 + c)*3)*DD;
        lf += p[d]; rt += p[DD + d]; gl += p[2*DD + d];
    }
    int ml = mlen[b];
    float mo = 0.f;
    for (int i = 0; i < MMOT; i++)
        if (i < ml) mo += emb[(size_t)mot[b*MMOT + i]*DD + d];
    mo /= (float)(ml > 1 ? ml : 1);
    float lden = (float)(ws[b] > 1 ? ws[b] : 1);
    int rc = LL - we[b];
    float rden = (float)(rc > 1 ? rc : 1);
    float* o = g_condin + (size_t)b*4*DD;
    o[d]        = mo;
    o[DD + d]   = lf / lden;
    o[2*DD + d] = rt / rden;
    o[3*DD + d] = gl / (float)LL;
    int k = d % (DD/2);
    float f = expf(-logf(10000.f) * (float)k / (float)(DD/2 - 1));
    float a = t[b] * f;
    g_tin[b*DD + d] = (d < DD/2) ? sinf(a) : cosf(a);
}

// ------------------- small fp32 GEMMs: warp per (column, row-pair) -----------
__global__ void gemm_small4(const float* __restrict__ tpW, const float* __restrict__ tpB,
                            const float* __restrict__ cpW, const float* __restrict__ cpB) {
    int gw = blockIdx.x*8 + (threadIdx.x >> 5);
    int lane = threadIdx.x & 31;
    const float* A; const float* Wt; const float* bias; float* C; int K; int col;
    if (gw < 4096) { A = g_tin;    Wt = tpW; bias = tpB; C = g_temb;    K = 512;  col = gw >> 3; }
    else           { A = g_condin; Wt = cpW; bias = cpB; C = g_condout; K = 2048; col = (gw - 4096) >> 3; }
    int row0 = (gw & 7)*2;
    const float* w = Wt + (size_t)col*K;
    float b = bias[col];
#pragma unroll
    for (int rr = 0; rr < 2; rr++) {
        int row = row0 + rr;
        const float* a = A + (size_t)row*K;
        float s = 0.f;
        for (int k = lane*4; k < K; k += 128) {
            float4 av = *(const float4*)(a + k);
            float4 wv = *(const float4*)(w + k);
            s += av.x*wv.x + av.y*wv.y + av.z*wv.z + av.w*wv.w;
        }
#pragma unroll
        for (int off = 16; off; off >>= 1) s += __shfl_xor_sync(0xffffffffu, s, off);
        if (lane == 0) C[(size_t)row*DD + col] = s + b;
    }
}

// ------------------- fused build: x_t/x1/x + cond rows + compaction ----------
__global__ void build_all2(const int* __restrict__ tok, const int* __restrict__ ws,
                           const int* __restrict__ we, const float* __restrict__ t,
                           const float* __restrict__ x0, const float* __restrict__ emb) {
    int bid = blockIdx.x;
    int tid = threadIdx.x;
    if (bid < 4096) {
        int idx = bid*256 + tid;
        int d = idx % DD; int r = idx / DD; int j = r % WIN; int b = r / WIN;
        int s0 = ws[b];
        int act = we[b] - s0;
        float x1v = 0.f;
        if (j < act) {
            int tk = tok[b*LL + s0 + j];
            x1v = emb[(size_t)tk*DD + d];
        }
        float tv = t[b];
        float xt = (1.f - tv)*x0[idx] + tv*x1v;
        g_x1[idx] = x1v;
        g_xt[idx] = xt;
        float xv = xt + g_temb[b*DD + d];
        int m = b*SS + 1 + j;
        g_x[(size_t)m*DD + d] = xv;
        g_xpk[pk(m, d, 8)] = __float2bfloat16(xv);
    } else if (bid < 4128) {
        int local = (bid - 4096)*256 + tid;
        int b = local >> 9, d = local & 511;
        float v = g_condout[b*DD + d];
        int m = b*SS;
        g_x[(size_t)m*DD + d] = v;
        g_xpk[pk(m, d, 8)] = __float2bfloat16(v);
    } else {
        __shared__ int off[BB+1];
        if (tid == 0) {
            off[0] = 0;
            for (int b = 0; b < BB; b++) {
                int a = we[b] - ws[b];
                if (a < 0) a = 0;
                if (a > WIN) a = WIN;
                off[b+1] = off[b] + a;
            }
            g_nvalid = off[BB];
        }
        __syncthreads();
        for (int idx = tid; idx < BB*WIN; idx += 256) {
            int b = idx / WIN, j = idx % WIN;
            int a = off[b+1] - off[b];
            if (j < a) {
                int r = off[b] + j;
                g_comporig[r]  = idx;
                g_amap[r]      = b*SS + 1 + j;
                g_complabel[r] = tok[b*LL + ws[b] + j];
            }
        }
    }
}

// ------------------- wmma (M=64 tile) GEMM -----------------------------------
using FragAcc = wmma::fragment<wmma::accumulator, 16, 16, 16, float>;
using FragA = wmma::fragment<wmma::matrix_a, 16, 16, 16, __nv_bfloat16, wmma::row_major>;
using FragB = wmma::fragment<wmma::matrix_b, 16, 16, 16, __nv_bfloat16, wmma::col_major>;

__device__ __forceinline__ void compute64(const __nv_bfloat16* sa, const __nv_bfloat16* sb,
                                          int warp_m, int warp_n, FragAcc (&acc)[2][2]) {
#pragma unroll
    for (int kk = 0; kk < 64; kk += 16) {
        FragA af[2];
#pragma unroll
        for (int am = 0; am < 2; am++)
            wmma::load_matrix_sync(af[am], sa + (warp_m*32 + am*16)*TROW + kk, TROW);
#pragma unroll
        for (int an = 0; an < 2; an++) {
            FragB bf;
            wmma::load_matrix_sync(bf, sb + (warp_n*32 + an*16)*TROW + kk, TROW);
#pragma unroll
            for (int am = 0; am < 2; am++)
                wmma::mma_sync(acc[am][an], af[am], bf, acc[am][an]);
        }
    }
}

__device__ __forceinline__ void mainloop64(const __nv_bfloat16* Abase,
        const __nv_bfloat16* Bbase, unsigned char* dynsm, int nk, int tid,
        int warp_m, int warp_n, FragAcc (&acc)[2][2]) {
    uint32_t mb = sptr(dynsm + 4*STG);
    if (tid == 0) {
        MBARRIER_INIT(mb,      1);
        MBARRIER_INIT(mb + 8,  1);
        MBARRIER_INIT(mb + 16, 1);
        MBARRIER_INIT(mb + 24, 1);
    }
    __syncthreads();
    if (tid == 0) {
        FENCE_PROXY_ASYNC();
#pragma unroll
        for (int s = 0; s < 3; s++) {
            MBARRIER_EXPECT_TX(mb + 8*s, STG);
            BULK_LOAD(sptr(dynsm + s*STG), Abase + (size_t)s*TILE_ELEMS, 64*TROW*2, mb + 8*s);
            BULK_LOAD(sptr(dynsm + s*STG + 64*TROW*2), Bbase + (size_t)s*TILE_ELEMS, 128*TROW*2, mb + 8*s);
        }
    }
    for (int i = 0; i < nk; i++) {
        int s = i & 3;
        int ph = (i >> 2) & 1;
        MBARRIER_WAIT_PARITY(mb + 8*s, ph);
        compute64((const __nv_bfloat16*)(dynsm + s*STG),
                  (const __nv_bfloat16*)(dynsm + s*STG + 64*TROW*2),
                  warp_m, warp_n, acc);
        __syncthreads();
        if (tid == 0 && i + 3 < nk) {
            FENCE_PROXY_ASYNC();
            int s2 = (i + 3) & 3;
            MBARRIER_EXPECT_TX(mb + 8*s2, STG);
            BULK_LOAD(sptr(dynsm + s2*STG), Abase + (size_t)(i+3)*TILE_ELEMS, 64*TROW*2, mb + 8*s2);
            BULK_LOAD(sptr(dynsm + s2*STG + 64*TROW*2), Bbase + (size_t)(i+3)*TILE_ELEMS, 128*TROW*2, mb + 8*s2);
        }
    }
}

__global__ void __launch_bounds__(256) gemm64(const __nv_bfloat16* __restrict__ Ap,
        const __nv_bfloat16* __restrict__ Wp, const float* __restrict__ bias,
        float* C, __nv_bfloat16* Cpk, int Mh, int N, int KC, int use_nv, int relu) {
    extern __shared__ __align__(16) unsigned char dynsm[];
    int Mact = use_nv ? g_nvalid : Mh;
    int by = blockIdx.y, bx = blockIdx.x;
    if (by*64 >= Mact) return;
    int tid = threadIdx.x, lane = tid & 31, wid = tid >> 5;
    int warp_m = wid & 1, warp_n = wid >> 1;

    FragAcc acc[2][2];
    for (int i = 0; i < 2; i++)
        for (int j = 0; j < 2; j++)
            wmma::fill_fragment(acc[i][j], 0.0f);

    const __nv_bfloat16* Abase = Ap + ((size_t)(by >> 1)*KC)*TILE_ELEMS + (size_t)(by & 1)*64*TROW;
    const __nv_bfloat16* Bbase = Wp + (size_t)bx*KC*TILE_ELEMS;
    mainloop64(Abase, Bbase, dynsm, KC, tid, warp_m, warp_n, acc);

    float* stage = ((float*)dynsm) + wid*256;
    int r = lane >> 1, halfc = (lane & 1)*8;
    int KCo = N >> 6;
    for (int am = 0; am < 2; am++) {
        for (int an = 0; an < 2; an++) {
            wmma::store_matrix_sync(stage, acc[am][an], 16, wmma::mem_row_major);
            __syncwarp();
            int grow = by*64 + warp_m*32 + am*16 + r;
            int gcol = bx*128 + warp_n*32 + an*16 + halfc;
            if (grow < Mact) {
                float v[8];
                for (int j = 0; j < 8; j++) {
                    v[j] = stage[r*16 + halfc + j] + bias[gcol + j];
                    if (relu) v[j] = fmaxf(v[j], 0.f);
                }
                if (C) {
                    float4* p = (float4*)(C + (size_t)grow*N + gcol);
                    p[0] = make_float4(v[0], v[1], v[2], v[3]);
                    p[1] = make_float4(v[4], v[5], v[6], v[7]);
                }
                if (Cpk) {
                    __nv_bfloat162 b0 = __float22bfloat162_rn(make_float2(v[0], v[1]));
                    __nv_bfloat162 b1 = __float22bfloat162_rn(make_float2(v[2], v[3]));
                    __nv_bfloat162 b2 = __float22bfloat162_rn(make_float2(v[4], v[5]));
                    __nv_bfloat162 b3 = __float22bfloat162_rn(make_float2(v[6], v[7]));
                    uint4 u;
                    u.x = *(uint32_t*)&b0; u.y = *(uint32_t*)&b1;
                    u.z = *(uint32_t*)&b2; u.w = *(uint32_t*)&b3;
                    *(uint4*)(Cpk + pk(grow, gcol, KCo)) = u;
                }
            }
            __syncwarp();
        }
    }
}

// ------------------- decode GEMM (M=64) + fused online-softmax ---------------
__global__ void __launch_bounds__(256) decode64(const __nv_bfloat16* __restrict__ Ap,
        const __nv_bfloat16* __restrict__ Wp, const float* __restrict__ bias) {
    extern __shared__ __align__(16) unsigned char dynsm[];
    __shared__ float bias_s[128];
    __shared__ float2 red[64][4];
    int Mact = g_nvalid;
    int by = blockIdx.y, bx = blockIdx.x;
    if (by*64 >= Mact) return;
    int tid = threadIdx.x, lane = tid & 31, wid = tid >> 5;
    int warp_m = wid & 1, warp_n = wid >> 1;
    if (tid < 128) bias_s[tid] = bias[bx*128 + tid];

    FragAcc acc[2][2];
    for (int i = 0; i < 2; i++)
        for (int j = 0; j < 2; j++)
            wmma::fill_fragment(acc[i][j], 0.0f);

    const int KC = DD/64;
    const __nv_bfloat16* Abase = Ap + ((size_t)(by >> 1)*KC)*TILE_ELEMS + (size_t)(by & 1)*64*TROW;
    const __nv_bfloat16* Bbase = Wp + (size_t)bx*KC*TILE_ELEMS;
    mainloop64(Abase, Bbase, dynsm, KC, tid, warp_m, warp_n, acc);

    float* stage = ((float*)dynsm) + wid*256;
    int r = lane >> 1, halfc = (lane & 1)*8;
    float rm[2], rs[2];
    rm[0] = rm[1] = -1e30f; rs[0] = rs[1] = 0.f;
    for (int am = 0; am < 2; am++) {
        for (int an = 0; an < 2; an++) {
            wmma::store_matrix_sync(stage, acc[am][an], 16, wmma::mem_row_major);
            __syncwarp();
            int coll = warp_n*32 + an*16 + halfc;
            float vv[8];
            float mx = -1e30f;
            for (int j = 0; j < 8; j++) {
                vv[j] = stage[r*16 + halfc + j] + bias_s[coll + j];
                mx = fmaxf(mx, vv[j]);
            }
            float mxo = __shfl_xor_sync(0xffffffffu, mx, 1);
            float mxa = fmaxf(mx, mxo);
            float se = 0.f;
            for (int j = 0; j < 8; j++) se += expf(vv[j] - mxa);
            se += __shfl_xor_sync(0xffffffffu, se, 1);
            if (mxa > rm[am]) { rs[am] = rs[am]*expf(rm[am] - mxa) + se; rm[am] = mxa; }
            else              { rs[am] += se*expf(mxa - rm[am]); }
            __syncwarp();
        }
    }
    for (int am = 0; am < 2; am++) {
        int rl = warp_m*32 + am*16 + r;
        if ((lane & 1) == 0) red[rl][warp_n] = make_float2(rm[am], rs[am]);
    }
    __syncthreads();
    if (tid < 64) {
        int grow = by*64 + tid;
        if (grow < Mact) {
            float m = -1e30f, s = 0.f;
            for (int w = 0; w < 4; w++) {
                float2 p = red[tid][w];
                if (p.x > m) { s = s*expf(m - p.x) + p.y; m = p.x; }
                else         { s += p.y*expf(p.x - m); }
            }
            g_smpart[(size_t)grow*NCH2 + bx] = make_float2(m, s);
        }
    }
}

// ------------------- fused attention (scores + softmax + ctx, 1 kernel) ------
__global__ void attn_fused() {
    extern __shared__ float dynf[];          // sc[SCPAD] then kv[SS*HD] (16B aligned)
    float* sc = dynf;
    float* kv = dynf + SCPAD;
    int bh = blockIdx.x; int b = bh / HH, h = bh % HH;
    const float* base = g_qkv + (size_t)b*SS*3*DD;
    for (int i = threadIdx.x; i < SS*HD; i += blockDim.x) {
        int s = i / HD, d = i % HD;
        kv[s*HD + d] = base[(size_t)s*3*DD + DD + h*HD + d];
    }
    __syncthreads();
    int q = threadIdx.x;
    if (q < SS) {
        float qr[HD];
#pragma unroll
        for (int d = 0; d < HD; d++) qr[d] = base[(size_t)q*3*DD + h*HD + d];
        float* srow = sc + q*SS;
        float mx = -1e30f;
        for (int k = 0; k < SS; k++) {
            const float4* k4 = (const float4*)(kv + k*HD);
            float a = 0.f;
#pragma unroll
            for (int dq = 0; dq < 16; dq++) {
                float4 kvv = k4[dq];
                a += qr[4*dq+0]*kvv.x + qr[4*dq+1]*kvv.y + qr[4*dq+2]*kvv.z + qr[4*dq+3]*kvv.w;
            }
            a *= 0.125f;
            srow[k] = a;
            mx = fmaxf(mx, a);
        }
        float se = 0.f;
        for (int k = 0; k < SS; k++) {
            float e = expf(srow[k] - mx);
            srow[k] = e;
            se += e;
        }
        float inv = 1.f/se;
        for (int k = 0; k < SS; k++) srow[k] *= inv;
    }
    __syncthreads();
    const float* vb = base + 2*DD + h*HD;
    for (int i = threadIdx.x; i < SS*HD; i += blockDim.x) {
        int s = i / HD, d = i % HD;
        kv[s*HD + d] = vb[(size_t)s*3*DD + d];
    }
    __syncthreads();
    for (int i = threadIdx.x; i < SS*(HD/2); i += blockDim.x) {
        int qq = i / (HD/2), dp = i % (HD/2);
        const float* pr = sc + qq*SS;
        float a0 = 0.f, a1 = 0.f;
        for (int k = 0; k < SS; k++) {
            float pkv = pr[k];
            float2 v = *(const float2*)(kv + k*HD + 2*dp);
            a0 += pkv*v.x; a1 += pkv*v.y;
        }
        int m = b*SS + qq;
        __nv_bfloat162 o = __float22bfloat162_rn(make_float2(a0, a1));
        *(__nv_bfloat162*)(g_ctxpk + (((size_t)(m >> 7)*8 + h)*TILE_ELEMS
                           + (size_t)(m & 127)*TROW + 2*dp)) = o;
    }
}

// ------------------- residual + layernorm ------------------------------------
__global__ void ln_kernel(float* __restrict__ x, __nv_bfloat16* __restrict__ xpk,
                          const float* __restrict__ add,
                          const float* __restrict__ gam, const float* __restrict__ bet) {
    __shared__ float red[256];
    __shared__ float stats[2];
    int tid = threadIdx.x;
    int row = blockIdx.x;
    float2 xv = ((float2*)(x + (size_t)row*DD))[tid];
    float2 av = ((const float2*)(add + (size_t)row*DD))[tid];
    float v0 = xv.x + av.x;
    float v1 = xv.y + av.y;
    red[tid] = v0 + v1;
    __syncthreads();
    for (int st = 128; st; st >>= 1) { if (tid < st) red[tid] += red[tid+st]; __syncthreads(); }
    if (tid == 0) stats[0] = red[0] * (1.f/DD);
    __syncthreads();
    float mean = stats[0];
    float d0 = v0 - mean, d1 = v1 - mean;
    red[tid] = d0*d0 + d1*d1;
    __syncthreads();
    for (int st = 128; st; st >>= 1) { if (tid < st) red[tid] += red[tid+st]; __syncthreads(); }
    if (tid == 0) stats[1] = rsqrtf(red[0]*(1.f/DD) + EPSV);
    __syncthreads();
    float inv = stats[1];
    float o0 = d0*inv*gam[2*tid]   + bet[2*tid];
    float o1 = d1*inv*gam[2*tid+1] + bet[2*tid+1];
    ((float2*)(x + (size_t)row*DD))[tid] = make_float2(o0, o1);
    __nv_bfloat162 ob = __float22bfloat162_rn(make_float2(o0, o1));
    *(__nv_bfloat162*)(xpk + pk(row, 2*tid, 8)) = ob;
}

// ------------------- velocity loss partials + pred_x1 ------------------------
__global__ void velpred_kernel(const float* __restrict__ t, const float* __restrict__ x0) {
    int nv = g_nvalid;
    int total = nv * DD;
    float lsum = 0.f;
    for (int e = blockIdx.x*blockDim.x + threadIdx.x; e < total; e += gridDim.x*blockDim.x) {
        int r = e / DD, d = e % DD;
        int orig = g_comporig[r];
        int b = orig / WIN;
        int j = orig % WIN;
        float pv = g_predv[((size_t)(b*SS + 1 + j))*DD + d];
        float diff = pv - (g_x1[(size_t)orig*DD + d] - x0[(size_t)orig*DD + d]);
        lsum += diff*diff;
        g_px1pk[pk(r, d, 8)] = __float2bfloat16(g_xt[(size_t)orig*DD + d] + (1.f - t[b])*pv);
    }
    __shared__ float sm[256];
    sm[threadIdx.x] = lsum;
    __syncthreads();
    for (int st = 128; st; st >>= 1) { if (threadIdx.x < st) sm[threadIdx.x] += sm[threadIdx.x+st]; __syncthreads(); }
    if (threadIdx.x == 0) g_velred[blockIdx.x] = sm[0];
}

// ------------------- picked logit (packed operands) --------------------------
__global__ void picked_kernel(const float* __restrict__ decB) {
    int r = blockIdx.x*8 + threadIdx.x/32;
    int lane = threadIdx.x % 32;
    if (r >= g_nvalid) return;
    int lab = g_complabel[r];
    float s = 0.f;
    for (int i = lane; i < DD; i += 32) {
        __nv_bfloat16 a = g_habpk[pk(r, i, 8)];
        __nv_bfloat16 w = g_wdecP[pk(lab, i, 8)];
        s += __bfloat162float(a) * __bfloat162float(w);
    }
#pragma unroll
    for (int off = 16; off; off >>= 1) s += __shfl_xor_sync(0xffffffffu, s, off);
    if (lane == 0) g_picked[r] = s + decB[lab];
}

// ------------------- logsumexp combine ---------------------------------------
__global__ void combine_kernel() {
    int r = blockIdx.x;
    int nv = g_nvalid;
    float m = -1e30f, s = 0.f;
    if (r < nv) {
        for (int i = threadIdx.x; i < NCH2; i += blockDim.x) {
            float2 p = g_smpart[(size_t)r*NCH2 + i];
            if (p.x > m) { s = s*expf(m - p.x) + p.y; m = p.x; }
            else         { s += p.y*expf(p.x - m); }
        }
    }
    __shared__ float sm[128], ss[128];
    sm[threadIdx.x] = m; ss[threadIdx.x] = s;
    __syncthreads();
    for (int st = 64; st; st >>= 1) {
        if (threadIdx.x < st) {
            float m1 = sm[threadIdx.x], s1 = ss[threadIdx.x];
            float m2 = sm[threadIdx.x+st], s2 = ss[threadIdx.x+st];
            float M = fmaxf(m1, m2);
            sm[threadIdx.x] = M;
            ss[threadIdx.x] = s1*expf(m1 - M) + s2*expf(m2 - M);
        }
        __syncthreads();
    }
    if (threadIdx.x == 0) {
        if (r < nv) {
            float lse = sm[0] + logf(ss[0]);
            g_rowrecon[r] = lse - g_picked[r];
        } else {
            g_rowrecon[r] = 0.f;
        }
    }
}

// ------------------- final loss ----------------------------------------------
__global__ void final_kernel(float* __restrict__ out) {
    __shared__ float sm[256];
    int tid = threadIdx.x;
    int nv = g_nvalid;
    sm[tid] = g_velred[tid];
    __syncthreads();
    for (int st = 128; st; st >>= 1) { if (tid < st) sm[tid] += sm[tid+st]; __syncthreads(); }
    float vel = sm[0] / ((float)nv * (float)DD);
    __syncthreads();
    float r = 0.f;
    for (int i = tid; i < nv; i += 256) r += g_rowrecon[i];
    sm[tid] = r;
    __syncthreads();
    for (int st = 128; st; st >>= 1) { if (tid < st) sm[tid] += sm[tid+st]; __syncthreads(); }
    if (tid == 0) out[0] = vel + 0.1f * (sm[0] / (float)nv);
}

// ------------------- host side -----------------------------------------------
extern "C" void kernel_launch(void* const* d_in, const int* in_sizes, int n_in,
                              void* d_out, int out_size) {
    (void)in_sizes; (void)n_in; (void)out_size;
    const int*   tok       = (const int*)  d_in[0];
    const int*   motif_ids = (const int*)  d_in[1];
    const int*   motif_len = (const int*)  d_in[2];
    const int*   ws        = (const int*)  d_in[3];
    const int*   we        = (const int*)  d_in[4];
    const float* t         = (const float*)d_in[5];
    const float* x0        = (const float*)d_in[6];
    const float* emb       = (const float*)d_in[7];
    const float* decW      = (const float*)d_in[8];
    const float* decB      = (const float*)d_in[9];
    const float* adW       = (const float*)d_in[10];
    const float* adB       = (const float*)d_in[11];
    const float* tpW       = (const float*)d_in[12];
    const float* tpB       = (const float*)d_in[13];
    const float* cpW       = (const float*)d_in[14];
    const float* cpB       = (const float*)d_in[15];
    const float* qkvW      = (const float*)d_in[16];
    const float* qkvB      = (const float*)d_in[17];
    const float* aoW       = (const float*)d_in[18];
    const float* aoB       = (const float*)d_in[19];
    const float* f1W       = (const float*)d_in[20];
    const float* f1B       = (const float*)d_in[21];
    const float* f2W       = (const float*)d_in[22];
    const float* f2B       = (const float*)d_in[23];
    const float* ln1g      = (const float*)d_in[24];
    const float* ln1b      = (const float*)d_in[25];
    const float* ln2g      = (const float*)d_in[26];
    const float* ln2b      = (const float*)d_in[27];
    const float* outW      = (const float*)d_in[28];
    const float* outB      = (const float*)d_in[29];

    static bool inited = false;
    static float *p_x, *p_tmp, *p_predv, *p_qkv;
    static __nv_bfloat16 *p_xpk, *p_ctxpk, *p_ffpk, *p_px1pk, *p_habpk;
    static __nv_bfloat16 *p_wqkvP, *p_waoP, *p_wf1P, *p_wf2P, *p_woutP, *p_wadP, *p_wdecP;
    static cudaStream_t s2;
    static cudaEvent_t evFork, evJoin;
    if (!inited) {
        cudaGetSymbolAddress((void**)&p_x,      g_x);
        cudaGetSymbolAddress((void**)&p_tmp,    g_tmp);
        cudaGetSymbolAddress((void**)&p_predv,  g_predv);
        cudaGetSymbolAddress((void**)&p_qkv,    g_qkv);
        cudaGetSymbolAddress((void**)&p_xpk,    g_xpk);
        cudaGetSymbolAddress((void**)&p_ctxpk,  g_ctxpk);
        cudaGetSymbolAddress((void**)&p_ffpk,   g_ffpk);
        cudaGetSymbolAddress((void**)&p_px1pk,  g_px1pk);
        cudaGetSymbolAddress((void**)&p_habpk,  g_habpk);
        cudaGetSymbolAddress((void**)&p_wqkvP,  g_wqkvP);
        cudaGetSymbolAddress((void**)&p_waoP,   g_waoP);
        cudaGetSymbolAddress((void**)&p_wf1P,   g_wf1P);
        cudaGetSymbolAddress((void**)&p_wf2P,   g_wf2P);
        cudaGetSymbolAddress((void**)&p_woutP,  g_woutP);
        cudaGetSymbolAddress((void**)&p_wadP,   g_wadP);
        cudaGetSymbolAddress((void**)&p_wdecP,  g_wdecP);
        cudaFuncSetAttribute(gemm64, cudaFuncAttributeMaxDynamicSharedMemorySize, DYNSM);
        cudaFuncSetAttribute(decode64, cudaFuncAttributeMaxDynamicSharedMemorySize, DYNSM);
        cudaFuncSetAttribute(attn_fused, cudaFuncAttributeMaxDynamicSharedMemorySize, ATTSMEM);
        cudaStreamCreateWithFlags(&s2, cudaStreamNonBlocking);
        cudaEventCreateWithFlags(&evFork, cudaEventDisableTiming);
        cudaEventCreateWithFlags(&evJoin, cudaEventDisableTiming);
        inited = true;
    }

    // fork: weight packing on s2, preamble on main stream (independent work)
    cudaEventRecord(evFork, 0);
    cudaStreamWaitEvent(s2, evFork, 0);
    wpack_all<<<12864, 256, 0, s2>>>(qkvW, aoW, f1W, f2W, outW, adW, decW);
    cudaEventRecord(evJoin, s2);

    // preamble (no packed-weight dependency)
    pool_partial<<<dim3(BB, 8), 512>>>(tok, ws, we, emb);
    prep_kernel<<<BB, 512>>>(motif_ids, motif_len, ws, we, emb, t);
    gemm_small4<<<1024, 256>>>(tpW, tpB, cpW, cpB);
    build_all2<<<4129, 256>>>(tok, ws, we, t, x0, emb);

    // join: packed weights needed from here on
    cudaStreamWaitEvent(0, evJoin, 0);

    // transformer layers
    for (int i = 0; i < NLAYER; i++) {
        gemm64<<<dim3(12, 34), 256, DYNSM>>>(
            p_xpk, p_wqkvP + (size_t)i*12*8*TILE_ELEMS, qkvB + (size_t)i*3*DD,
            p_qkv, (__nv_bfloat16*)0, RT, 3*DD, 8, 0, 0);
        attn_fused<<<BB*HH, 256, ATTSMEM>>>();
        gemm64<<<dim3(4, 34), 256, DYNSM>>>(
            p_ctxpk, p_waoP + (size_t)i*4*8*TILE_ELEMS, aoB + (size_t)i*DD,
            p_tmp, (__nv_bfloat16*)0, RT, DD, 8, 0, 0);
        ln_kernel<<<RT, 256>>>(p_x, p_xpk, p_tmp, ln1g + (size_t)i*DD, ln1b + (size_t)i*DD);
        gemm64<<<dim3(16, 34), 256, DYNSM>>>(
            p_xpk, p_wf1P + (size_t)i*16*8*TILE_ELEMS, f1B + (size_t)i*FF,
            (float*)0, p_ffpk, RT, FF, 8, 0, 1);
        gemm64<<<dim3(4, 34), 256, DYNSM>>>(
            p_ffpk, p_wf2P + (size_t)i*4*32*TILE_ELEMS, f2B + (size_t)i*DD,
            p_tmp, (__nv_bfloat16*)0, RT, DD, 32, 0, 0);
        ln_kernel<<<RT, 256>>>(p_x, p_xpk, p_tmp, ln2g + (size_t)i*DD, ln2b + (size_t)i*DD);
    }

    // pred_v over all transformer rows (valid rows consumed by velpred)
    gemm64<<<dim3(4, 34), 256, DYNSM>>>(
        p_xpk, p_woutP, outB, p_predv, (__nv_bfloat16*)0, RT, DD, 8, 0, 0);
    velpred_kernel<<<256, 256>>>(t, x0);
    // adapter over compact valid rows -> packed hab
    gemm64<<<dim3(4, 32), 256, DYNSM>>>(
        p_px1pk, p_wadP, adB, (float*)0, p_habpk, WR, DD, 8, 1, 0);
    // decode GEMM with fused online softmax partials
    decode64<<<dim3(NCH2, 32), 256, DYNSM>>>(p_habpk, p_wdecP, decB);
    picked_kernel<<<WR/8, 256>>>(decB);
    combine_kernel<<<WR, 128>>>();
    final_kernel<<<1, 256>>>((float*)d_out);
}

// round 17
// speedup vs baseline: 1.5493x; 1.5493x over previous
#include <cuda_runtime.h>
#include <cuda_bf16.h>
#include <mma.h>
#include <math.h>
#include <stdint.h>

using namespace nvcuda;

#define BB 16
#define LL 2048
#define WIN 128
#define DD 512
#define HH 8
#define HD 64
#define FF 2048
#define NLAYER 3
#define VV 32000
#define MMOT 32
#define SS 129            // WIN + 1 (cond row)
#define RT (BB*SS)        // 2064 transformer rows
#define RTP 2176          // RT padded to 128
#define WR (BB*WIN)       // 2048 window rows
#define EPSV 1e-5f
#define NCH2 (VV/128)     // 250 softmax partial chunks

#define TROW 72                    // padded tile row stride (elems)
#define TILE_ELEMS (128*TROW)      // 9216
#define STG (64*TROW*2 + 128*TROW*2)   // 27648 bytes per stage (A64 + B128)
#define DYNSM (4*STG + 32)
#define SCPAD 16644                // SS*SS=16641 padded to mult of 4 (16B align for kv)
#define ATTSMEM ((SCPAD + SS*HD)*4)    // 99600 bytes

// ---------------- mbarrier / bulk-copy PTX macros ----------------------------
#define MBARRIER_INIT(mbar_smem_addr, count) \
    asm volatile("mbarrier.init.shared.b64 [%0], %1;" \
        :: "r"((uint32_t)(mbar_smem_addr)), "r"((uint32_t)(count)) : "memory")

#define MBARRIER_EXPECT_TX(mbar_smem_addr, tx_bytes) \
    asm volatile("mbarrier.arrive.expect_tx.shared.b64 _, [%0], %1;" \
        :: "r"((uint32_t)(mbar_smem_addr)), "r"((uint32_t)(tx_bytes)) : "memory")

#define MBARRIER_WAIT_PARITY(mbar_smem_addr, phase_parity) do { \
    uint32_t _mbar = (uint32_t)(mbar_smem_addr); \
    uint32_t _parity = (uint32_t)(phase_parity); \
    uint32_t _done; \
    asm volatile( \
        "{\n\t" \
        ".reg .pred p;\n\t" \
        "mbarrier.try_wait.parity.acquire.cta.shared::cta.b64 p, [%1], %2;\n\t" \
        "selp.b32 %0, 1, 0, p;\n\t" \
        "}" \
        : "=r"(_done) : "r"(_mbar), "r"(_parity) : "memory"); \
    if (!_done) { \
        asm volatile( \
            "{\n\t" \
            ".reg .pred P1;\n\t" \
            "WAIT_LOOP_%=:\n\t" \
            "mbarrier.try_wait.parity.acquire.cta.shared::cta.b64 P1, [%0], %1, 0x989680;\n\t" \
            "@P1 bra.uni WAIT_DONE_%=;\n\t" \
            "bra.uni WAIT_LOOP_%=;\n\t" \
            "WAIT_DONE_%=:\n\t" \
            "}" \
            :: "r"(_mbar), "r"(_parity) : "memory"); \
    } \
} while(0)

#define BULK_LOAD(dst_smem, src_gmem, nbytes, mbar_smem) \
    asm volatile("cp.async.bulk.shared::cluster.global.mbarrier::complete_tx::bytes [%0], [%1], %2, [%3];" \
        :: "r"((uint32_t)(dst_smem)), "l"(src_gmem), "r"((uint32_t)(nbytes)), \
           "r"((uint32_t)(mbar_smem)) : "memory")

#define FENCE_PROXY_ASYNC() \
    asm volatile("fence.proxy.async.shared::cta;" ::: "memory")

__device__ __forceinline__ uint32_t sptr(const void* p) {
    return (uint32_t)__cvta_generic_to_shared(p);
}

// packed layout offset: tiles [m/128][k/64] of [128][TROW]
__device__ __forceinline__ size_t pk(int m, int k, int KC) {
    return ((size_t)(m >> 7)*KC + (k >> 6))*TILE_ELEMS + (size_t)(m & 127)*TROW + (k & 63);
}

// ------------------- device scratch (static, no allocation) -------------------
__device__ float g_condin[BB*4*DD];
__device__ float g_poolpart[BB*8*3*DD];
__device__ float g_tin[BB*DD];
__device__ float g_temb[BB*DD];
__device__ float g_condout[BB*DD];
__device__ float g_x[RT*DD];
__device__ float g_xt[WR*DD];
__device__ float g_x1[WR*DD];
__device__ float g_qkv[RT*3*DD];
__device__ float g_tmp[RT*DD];
__device__ float g_predv[RTP*DD];
__device__ float2 g_smpart[(size_t)WR*NCH2];
__device__ float g_picked[WR];
__device__ float g_rowrecon[WR];
__device__ float g_velred[256];
__device__ int g_comporig[WR];
__device__ int g_complabel[WR];
__device__ int g_amap[WR];
__device__ int g_nvalid;

// packed bf16 activations
__device__ __align__(16) __nv_bfloat16 g_xpk[17*8*TILE_ELEMS];
__device__ __align__(16) __nv_bfloat16 g_ctxpk[17*8*TILE_ELEMS];
__device__ __align__(16) __nv_bfloat16 g_ffpk[17*32*TILE_ELEMS];
__device__ __align__(16) __nv_bfloat16 g_px1pk[16*8*TILE_ELEMS];
__device__ __align__(16) __nv_bfloat16 g_habpk[16*8*TILE_ELEMS];
// packed bf16 weights
__device__ __align__(16) __nv_bfloat16 g_wqkvP[NLAYER*12*8*TILE_ELEMS];
__device__ __align__(16) __nv_bfloat16 g_waoP[NLAYER*4*8*TILE_ELEMS];
__device__ __align__(16) __nv_bfloat16 g_wf1P[NLAYER*16*8*TILE_ELEMS];
__device__ __align__(16) __nv_bfloat16 g_wf2P[NLAYER*4*32*TILE_ELEMS];
__device__ __align__(16) __nv_bfloat16 g_woutP[4*8*TILE_ELEMS];
__device__ __align__(16) __nv_bfloat16 g_wadP[4*8*TILE_ELEMS];
__device__ __align__(16) __nv_bfloat16 g_wdecP[250*8*TILE_ELEMS];

// ------------------- fused weight packing ------------------------------------
__device__ __forceinline__ void packone(const float4* __restrict__ W,
                                        __nv_bfloat16* __restrict__ dst, int idx, int K) {
    int ck = K >> 3;
    int n = idx / ck, q = idx - n*ck;
    int k = q << 3;
    int kc = k >> 6, c8 = (k >> 3) & 7;
    int KC = K >> 6;
    size_t doff = ((size_t)(n >> 7)*KC + kc)*TILE_ELEMS + (size_t)(n & 127)*TROW + c8*8;
    float4 a = W[(size_t)idx*2], b = W[(size_t)idx*2 + 1];
    __nv_bfloat162 r0 = __float22bfloat162_rn(make_float2(a.x, a.y));
    __nv_bfloat162 r1 = __float22bfloat162_rn(make_float2(a.z, a.w));
    __nv_bfloat162 r2 = __float22bfloat162_rn(make_float2(b.x, b.y));
    __nv_bfloat162 r3 = __float22bfloat162_rn(make_float2(b.z, b.w));
    uint4 v;
    v.x = *(uint32_t*)&r0; v.y = *(uint32_t*)&r1;
    v.z = *(uint32_t*)&r2; v.w = *(uint32_t*)&r3;
    ((uint4*)dst)[doff >> 3] = v;
}

__global__ void wpack_all(const float* qkvW, const float* aoW, const float* f1W,
                          const float* f2W, const float* outW, const float* adW,
                          const float* decW) {
    int idx = blockIdx.x*blockDim.x + threadIdx.x;
    if      (idx <  294912) packone((const float4*)qkvW, g_wqkvP, idx,           512);
    else if (idx <  393216) packone((const float4*)aoW,  g_waoP,  idx - 294912,  512);
    else if (idx <  786432) packone((const float4*)f1W,  g_wf1P,  idx - 393216,  512);
    else if (idx < 1179648) packone((const float4*)f2W,  g_wf2P,  idx - 786432,  2048);
    else if (idx < 1212416) packone((const float4*)outW, g_woutP, idx - 1179648, 512);
    else if (idx < 1245184) packone((const float4*)adW,  g_wadP,  idx - 1212416, 512);
    else if (idx < 3293184) packone((const float4*)decW, g_wdecP, idx - 1245184, 512);
}

// ------------------- pools -----------------------------------------------------
__global__ void pool_partial(const int* __restrict__ tok, const int* __restrict__ ws,
                             const int* __restrict__ we, const float* __restrict__ emb) {
    int b = blockIdx.x, c = blockIdx.y, d = threadIdx.x;
    int s0 = ws[b], e0 = we[b];
    float gl = 0.f, lf = 0.f, rt = 0.f;
    int l0 = c * (LL/8);
#pragma unroll 4
    for (int i = 0; i < LL/8; i++) {
        int l = l0 + i;
        int t = tok[b*LL + l];
        float v = emb[(size_t)t*DD + d];
        gl += v;
        if (l < s0)  lf += v;
        if (l >= e0) rt += v;
    }
    float* p = g_poolpart + ((size_t)(b*8 + c)*3)*DD;
    p[d] = lf; p[DD + d] = rt; p[2*DD + d] = gl;
}

__global__ void prep_kernel(const int* __restrict__ mot, const int* __restrict__ mlen,
                            const int* __restrict__ ws, const int* __restrict__ we,
                            const float* __restrict__ emb, const float* __restrict__ t) {
    int b = blockIdx.x, d = threadIdx.x;
    float lf = 0.f, rt = 0.f, gl = 0.f;
    for (int c = 0; c < 8; c++) {
        const float* p = g_poolpart + ((size_t)(b*8 + c)*3)*DD;
        lf += p[d]; rt += p[DD + d]; gl += p[2*DD + d];
    }
    int ml = mlen[b];
    float mo = 0.f;
    for (int i = 0; i < MMOT; i++)
        if (i < ml) mo += emb[(size_t)mot[b*MMOT + i]*DD + d];
    mo /= (float)(ml > 1 ? ml : 1);
    float lden = (float)(ws[b] > 1 ? ws[b] : 1);
    int rc = LL - we[b];
    float rden = (float)(rc > 1 ? rc : 1);
    float* o = g_condin + (size_t)b*4*DD;
    o[d]        = mo;
    o[DD + d]   = lf / lden;
    o[2*DD + d] = rt / rden;
    o[3*DD + d] = gl / (float)LL;
    int k = d % (DD/2);
    float f = expf(-logf(10000.f) * (float)k / (float)(DD/2 - 1));
    float a = t[b] * f;
    g_tin[b*DD + d] = (d < DD/2) ? sinf(a) : cosf(a);
}

// ------------------- small fp32 GEMMs: warp per (column, row-pair) -----------
__global__ void gemm_small4(const float* __restrict__ tpW, const float* __restrict__ tpB,
                            const float* __restrict__ cpW, const float* __restrict__ cpB) {
    int gw = blockIdx.x*8 + (threadIdx.x >> 5);
    int lane = threadIdx.x & 31;
    const float* A; const float* Wt; const float* bias; float* C; int K; int col;
    if (gw < 4096) { A = g_tin;    Wt = tpW; bias = tpB; C = g_temb;    K = 512;  col = gw >> 3; }
    else           { A = g_condin; Wt = cpW; bias = cpB; C = g_condout; K = 2048; col = (gw - 4096) >> 3; }
    int row0 = (gw & 7)*2;
    const float* w = Wt + (size_t)col*K;
    float b = bias[col];
#pragma unroll
    for (int rr = 0; rr < 2; rr++) {
        int row = row0 + rr;
        const float* a = A + (size_t)row*K;
        float s = 0.f;
        for (int k = lane*4; k < K; k += 128) {
            float4 av = *(const float4*)(a + k);
            float4 wv = *(const float4*)(w + k);
            s += av.x*wv.x + av.y*wv.y + av.z*wv.z + av.w*wv.w;
        }
#pragma unroll
        for (int off = 16; off; off >>= 1) s += __shfl_xor_sync(0xffffffffu, s, off);
        if (lane == 0) C[(size_t)row*DD + col] = s + b;
    }
}

// ------------------- fused build: x_t/x1/x + cond rows + compaction ----------
__global__ void build_all2(const int* __restrict__ tok, const int* __restrict__ ws,
                           const int* __restrict__ we, const float* __restrict__ t,
                           const float* __restrict__ x0, const float* __restrict__ emb) {
    int bid = blockIdx.x;
    int tid = threadIdx.x;
    if (bid < 4096) {
        int idx = bid*256 + tid;
        int d = idx % DD; int r = idx / DD; int j = r % WIN; int b = r / WIN;
        int s0 = ws[b];
        int act = we[b] - s0;
        float x1v = 0.f;
        if (j < act) {
            int tk = tok[b*LL + s0 + j];
            x1v = emb[(size_t)tk*DD + d];
        }
        float tv = t[b];
        float xt = (1.f - tv)*x0[idx] + tv*x1v;
        g_x1[idx] = x1v;
        g_xt[idx] = xt;
        float xv = xt + g_temb[b*DD + d];
        int m = b*SS + 1 + j;
        g_x[(size_t)m*DD + d] = xv;
        g_xpk[pk(m, d, 8)] = __float2bfloat16(xv);
    } else if (bid < 4128) {
        int local = (bid - 4096)*256 + tid;
        int b = local >> 9, d = local & 511;
        float v = g_condout[b*DD + d];
        int m = b*SS;
        g_x[(size_t)m*DD + d] = v;
        g_xpk[pk(m, d, 8)] = __float2bfloat16(v);
    } else {
        __shared__ int off[BB+1];
        if (tid == 0) {
            off[0] = 0;
            for (int b = 0; b < BB; b++) {
                int a = we[b] - ws[b];
                if (a < 0) a = 0;
                if (a > WIN) a = WIN;
                off[b+1] = off[b] + a;
            }
            g_nvalid = off[BB];
        }
        __syncthreads();
        for (int idx = tid; idx < BB*WIN; idx += 256) {
            int b = idx / WIN, j = idx % WIN;
            int a = off[b+1] - off[b];
            if (j < a) {
                int r = off[b] + j;
                g_comporig[r]  = idx;
                g_amap[r]      = b*SS + 1 + j;
                g_complabel[r] = tok[b*LL + ws[b] + j];
            }
        }
    }
}

// ------------------- wmma (M=64 tile) GEMM -----------------------------------
using FragAcc = wmma::fragment<wmma::accumulator, 16, 16, 16, float>;
using FragA = wmma::fragment<wmma::matrix_a, 16, 16, 16, __nv_bfloat16, wmma::row_major>;
using FragB = wmma::fragment<wmma::matrix_b, 16, 16, 16, __nv_bfloat16, wmma::col_major>;

__device__ __forceinline__ void compute64(const __nv_bfloat16* sa, const __nv_bfloat16* sb,
                                          int warp_m, int warp_n, FragAcc (&acc)[2][2]) {
#pragma unroll
    for (int kk = 0; kk < 64; kk += 16) {
        FragA af[2];
#pragma unroll
        for (int am = 0; am < 2; am++)
            wmma::load_matrix_sync(af[am], sa + (warp_m*32 + am*16)*TROW + kk, TROW);
#pragma unroll
        for (int an = 0; an < 2; an++) {
            FragB bf;
            wmma::load_matrix_sync(bf, sb + (warp_n*32 + an*16)*TROW + kk, TROW);
#pragma unroll
            for (int am = 0; am < 2; am++)
                wmma::mma_sync(acc[am][an], af[am], bf, acc[am][an]);
        }
    }
}

__device__ __forceinline__ void mainloop64(const __nv_bfloat16* Abase,
        const __nv_bfloat16* Bbase, unsigned char* dynsm, int nk, int tid,
        int warp_m, int warp_n, FragAcc (&acc)[2][2]) {
    uint32_t mb = sptr(dynsm + 4*STG);
    if (tid == 0) {
        MBARRIER_INIT(mb,      1);
        MBARRIER_INIT(mb + 8,  1);
        MBARRIER_INIT(mb + 16, 1);
        MBARRIER_INIT(mb + 24, 1);
    }
    __syncthreads();
    if (tid == 0) {
        FENCE_PROXY_ASYNC();
#pragma unroll
        for (int s = 0; s < 3; s++) {
            MBARRIER_EXPECT_TX(mb + 8*s, STG);
            BULK_LOAD(sptr(dynsm + s*STG), Abase + (size_t)s*TILE_ELEMS, 64*TROW*2, mb + 8*s);
            BULK_LOAD(sptr(dynsm + s*STG + 64*TROW*2), Bbase + (size_t)s*TILE_ELEMS, 128*TROW*2, mb + 8*s);
        }
    }
    for (int i = 0; i < nk; i++) {
        int s = i & 3;
        int ph = (i >> 2) & 1;
        MBARRIER_WAIT_PARITY(mb + 8*s, ph);
        compute64((const __nv_bfloat16*)(dynsm + s*STG),
                  (const __nv_bfloat16*)(dynsm + s*STG + 64*TROW*2),
                  warp_m, warp_n, acc);
        __syncthreads();
        if (tid == 0 && i + 3 < nk) {
            FENCE_PROXY_ASYNC();
            int s2 = (i + 3) & 3;
            MBARRIER_EXPECT_TX(mb + 8*s2, STG);
            BULK_LOAD(sptr(dynsm + s2*STG), Abase + (size_t)(i+3)*TILE_ELEMS, 64*TROW*2, mb + 8*s2);
            BULK_LOAD(sptr(dynsm + s2*STG + 64*TROW*2), Bbase + (size_t)(i+3)*TILE_ELEMS, 128*TROW*2, mb + 8*s2);
        }
    }
}

__global__ void __launch_bounds__(256) gemm64(const __nv_bfloat16* __restrict__ Ap,
        const __nv_bfloat16* __restrict__ Wp, const float* __restrict__ bias,
        float* C, __nv_bfloat16* Cpk, int Mh, int N, int KC, int use_nv, int relu) {
    extern __shared__ __align__(16) unsigned char dynsm[];
    int Mact = use_nv ? g_nvalid : Mh;
    int by = blockIdx.y, bx = blockIdx.x;
    if (by*64 >= Mact) return;
    int tid = threadIdx.x, lane = tid & 31, wid = tid >> 5;
    int warp_m = wid & 1, warp_n = wid >> 1;

    FragAcc acc[2][2];
    for (int i = 0; i < 2; i++)
        for (int j = 0; j < 2; j++)
            wmma::fill_fragment(acc[i][j], 0.0f);

    const __nv_bfloat16* Abase = Ap + ((size_t)(by >> 1)*KC)*TILE_ELEMS + (size_t)(by & 1)*64*TROW;
    const __nv_bfloat16* Bbase = Wp + (size_t)bx*KC*TILE_ELEMS;
    mainloop64(Abase, Bbase, dynsm, KC, tid, warp_m, warp_n, acc);

    float* stage = ((float*)dynsm) + wid*256;
    int r = lane >> 1, halfc = (lane & 1)*8;
    int KCo = N >> 6;
    for (int am = 0; am < 2; am++) {
        for (int an = 0; an < 2; an++) {
            wmma::store_matrix_sync(stage, acc[am][an], 16, wmma::mem_row_major);
            __syncwarp();
            int grow = by*64 + warp_m*32 + am*16 + r;
            int gcol = bx*128 + warp_n*32 + an*16 + halfc;
            if (grow < Mact) {
                float v[8];
                for (int j = 0; j < 8; j++) {
                    v[j] = stage[r*16 + halfc + j] + bias[gcol + j];
                    if (relu) v[j] = fmaxf(v[j], 0.f);
                }
                if (C) {
                    float4* p = (float4*)(C + (size_t)grow*N + gcol);
                    p[0] = make_float4(v[0], v[1], v[2], v[3]);
                    p[1] = make_float4(v[4], v[5], v[6], v[7]);
                }
                if (Cpk) {
                    __nv_bfloat162 b0 = __float22bfloat162_rn(make_float2(v[0], v[1]));
                    __nv_bfloat162 b1 = __float22bfloat162_rn(make_float2(v[2], v[3]));
                    __nv_bfloat162 b2 = __float22bfloat162_rn(make_float2(v[4], v[5]));
                    __nv_bfloat162 b3 = __float22bfloat162_rn(make_float2(v[6], v[7]));
                    uint4 u;
                    u.x = *(uint32_t*)&b0; u.y = *(uint32_t*)&b1;
                    u.z = *(uint32_t*)&b2; u.w = *(uint32_t*)&b3;
                    *(uint4*)(Cpk + pk(grow, gcol, KCo)) = u;
                }
            }
            __syncwarp();
        }
    }
}

// ------------------- decode GEMM (M=64) + fused online-softmax ---------------
__global__ void __launch_bounds__(256) decode64(const __nv_bfloat16* __restrict__ Ap,
        const __nv_bfloat16* __restrict__ Wp, const float* __restrict__ bias) {
    extern __shared__ __align__(16) unsigned char dynsm[];
    __shared__ float bias_s[128];
    __shared__ float2 red[64][4];
    int Mact = g_nvalid;
    int by = blockIdx.y, bx = blockIdx.x;
    if (by*64 >= Mact) return;
    int tid = threadIdx.x, lane = tid & 31, wid = tid >> 5;
    int warp_m = wid & 1, warp_n = wid >> 1;
    if (tid < 128) bias_s[tid] = bias[bx*128 + tid];

    FragAcc acc[2][2];
    for (int i = 0; i < 2; i++)
        for (int j = 0; j < 2; j++)
            wmma::fill_fragment(acc[i][j], 0.0f);

    const int KC = DD/64;
    const __nv_bfloat16* Abase = Ap + ((size_t)(by >> 1)*KC)*TILE_ELEMS + (size_t)(by & 1)*64*TROW;
    const __nv_bfloat16* Bbase = Wp + (size_t)bx*KC*TILE_ELEMS;
    mainloop64(Abase, Bbase, dynsm, KC, tid, warp_m, warp_n, acc);

    float* stage = ((float*)dynsm) + wid*256;
    int r = lane >> 1, halfc = (lane & 1)*8;
    float rm[2], rs[2];
    rm[0] = rm[1] = -1e30f; rs[0] = rs[1] = 0.f;
    for (int am = 0; am < 2; am++) {
        for (int an = 0; an < 2; an++) {
            wmma::store_matrix_sync(stage, acc[am][an], 16, wmma::mem_row_major);
            __syncwarp();
            int coll = warp_n*32 + an*16 + halfc;
            float vv[8];
            float mx = -1e30f;
            for (int j = 0; j < 8; j++) {
                vv[j] = stage[r*16 + halfc + j] + bias_s[coll + j];
                mx = fmaxf(mx, vv[j]);
            }
            float mxo = __shfl_xor_sync(0xffffffffu, mx, 1);
            float mxa = fmaxf(mx, mxo);
            float se = 0.f;
            for (int j = 0; j < 8; j++) se += expf(vv[j] - mxa);
            se += __shfl_xor_sync(0xffffffffu, se, 1);
            if (mxa > rm[am]) { rs[am] = rs[am]*expf(rm[am] - mxa) + se; rm[am] = mxa; }
            else              { rs[am] += se*expf(mxa - rm[am]); }
            __syncwarp();
        }
    }
    for (int am = 0; am < 2; am++) {
        int rl = warp_m*32 + am*16 + r;
        if ((lane & 1) == 0) red[rl][warp_n] = make_float2(rm[am], rs[am]);
    }
    __syncthreads();
    if (tid < 64) {
        int grow = by*64 + tid;
        if (grow < Mact) {
            float m = -1e30f, s = 0.f;
            for (int w = 0; w < 4; w++) {
                float2 p = red[tid][w];
                if (p.x > m) { s = s*expf(m - p.x) + p.y; m = p.x; }
                else         { s += p.y*expf(p.x - m); }
            }
            g_smpart[(size_t)grow*NCH2 + bx] = make_float2(m, s);
        }
    }
}

// ------------------- fused attention (scores + softmax + ctx, 1 kernel) ------
__global__ void attn_fused() {
    extern __shared__ float dynf[];          // sc[SCPAD] then kv[SS*HD] (16B aligned)
    float* sc = dynf;
    float* kv = dynf + SCPAD;
    int bh = blockIdx.x; int b = bh / HH, h = bh % HH;
    const float* base = g_qkv + (size_t)b*SS*3*DD;
    for (int i = threadIdx.x; i < SS*HD; i += blockDim.x) {
        int s = i / HD, d = i % HD;
        kv[s*HD + d] = base[(size_t)s*3*DD + DD + h*HD + d];
    }
    __syncthreads();
    int q = threadIdx.x;
    if (q < SS) {
        float qr[HD];
#pragma unroll
        for (int d = 0; d < HD; d++) qr[d] = base[(size_t)q*3*DD + h*HD + d];
        float* srow = sc + q*SS;
        float mx = -1e30f;
        for (int k = 0; k < SS; k++) {
            const float4* k4 = (const float4*)(kv + k*HD);
            float a = 0.f;
#pragma unroll
            for (int dq = 0; dq < 16; dq++) {
                float4 kvv = k4[dq];
                a += qr[4*dq+0]*kvv.x + qr[4*dq+1]*kvv.y + qr[4*dq+2]*kvv.z + qr[4*dq+3]*kvv.w;
            }
            a *= 0.125f;
            srow[k] = a;
            mx = fmaxf(mx, a);
        }
        float se = 0.f;
        for (int k = 0; k < SS; k++) {
            float e = expf(srow[k] - mx);
            srow[k] = e;
            se += e;
        }
        float inv = 1.f/se;
        for (int k = 0; k < SS; k++) srow[k] *= inv;
    }
    __syncthreads();
    const float* vb = base + 2*DD + h*HD;
    for (int i = threadIdx.x; i < SS*HD; i += blockDim.x) {
        int s = i / HD, d = i % HD;
        kv[s*HD + d] = vb[(size_t)s*3*DD + d];
    }
    __syncthreads();
    for (int i = threadIdx.x; i < SS*(HD/2); i += blockDim.x) {
        int qq = i / (HD/2), dp = i % (HD/2);
        const float* pr = sc + qq*SS;
        float a0 = 0.f, a1 = 0.f;
        for (int k = 0; k < SS; k++) {
            float pkv = pr[k];
            float2 v = *(const float2*)(kv + k*HD + 2*dp);
            a0 += pkv*v.x; a1 += pkv*v.y;
        }
        int m = b*SS + qq;
        __nv_bfloat162 o = __float22bfloat162_rn(make_float2(a0, a1));
        *(__nv_bfloat162*)(g_ctxpk + (((size_t)(m >> 7)*8 + h)*TILE_ELEMS
                           + (size_t)(m & 127)*TROW + 2*dp)) = o;
    }
}

// ------------------- residual + layernorm (warp-per-row) ---------------------
__global__ void ln_warp(float* __restrict__ x, __nv_bfloat16* __restrict__ xpk,
                        const float* __restrict__ add,
                        const float* __restrict__ gam, const float* __restrict__ bet) {
    int warp = threadIdx.x >> 5, lane = threadIdx.x & 31;
    int row = blockIdx.x*8 + warp;
    if (row >= RT) return;
    const float4* xr = (const float4*)(x + (size_t)row*DD);
    const float4* ar = (const float4*)(add + (size_t)row*DD);
    float4 v[4];
    float sum = 0.f;
#pragma unroll
    for (int i = 0; i < 4; i++) {
        int idx = lane + i*32;
        float4 a = xr[idx], b = ar[idx];
        v[i] = make_float4(a.x + b.x, a.y + b.y, a.z + b.z, a.w + b.w);
        sum += v[i].x + v[i].y + v[i].z + v[i].w;
    }
#pragma unroll
    for (int off = 16; off; off >>= 1) sum += __shfl_xor_sync(0xffffffffu, sum, off);
    float mean = sum * (1.f/DD);
    float ssq = 0.f;
#pragma unroll
    for (int i = 0; i < 4; i++) {
        v[i].x -= mean; v[i].y -= mean; v[i].z -= mean; v[i].w -= mean;
        ssq += v[i].x*v[i].x + v[i].y*v[i].y + v[i].z*v[i].z + v[i].w*v[i].w;
    }
#pragma unroll
    for (int off = 16; off; off >>= 1) ssq += __shfl_xor_sync(0xffffffffu, ssq, off);
    float inv = rsqrtf(ssq*(1.f/DD) + EPSV);
    float4* xw = (float4*)(x + (size_t)row*DD);
#pragma unroll
    for (int i = 0; i < 4; i++) {
        int idx = lane + i*32;
        float4 g = ((const float4*)gam)[idx];
        float4 be = ((const float4*)bet)[idx];
        float o0 = v[i].x*inv*g.x + be.x;
        float o1 = v[i].y*inv*g.y + be.y;
        float o2 = v[i].z*inv*g.z + be.z;
        float o3 = v[i].w*inv*g.w + be.w;
        xw[idx] = make_float4(o0, o1, o2, o3);
        int k = idx*4;
        __nv_bfloat162* pp = (__nv_bfloat162*)(xpk + pk(row, k, 8));
        pp[0] = __float22bfloat162_rn(make_float2(o0, o1));
        pp[1] = __float22bfloat162_rn(make_float2(o2, o3));
    }
}

// ------------------- velocity loss partials + pred_x1 ------------------------
__global__ void velpred_kernel(const float* __restrict__ t, const float* __restrict__ x0) {
    int nv = g_nvalid;
    int total = nv * DD;
    float lsum = 0.f;
    for (int e = blockIdx.x*blockDim.x + threadIdx.x; e < total; e += gridDim.x*blockDim.x) {
        int r = e / DD, d = e % DD;
        int orig = g_comporig[r];
        int b = orig / WIN;
        int j = orig % WIN;
        float pv = g_predv[((size_t)(b*SS + 1 + j))*DD + d];
        float diff = pv - (g_x1[(size_t)orig*DD + d] - x0[(size_t)orig*DD + d]);
        lsum += diff*diff;
        g_px1pk[pk(r, d, 8)] = __float2bfloat16(g_xt[(size_t)orig*DD + d] + (1.f - t[b])*pv);
    }
    __shared__ float sm[256];
    sm[threadIdx.x] = lsum;
    __syncthreads();
    for (int st = 128; st; st >>= 1) { if (threadIdx.x < st) sm[threadIdx.x] += sm[threadIdx.x+st]; __syncthreads(); }
    if (threadIdx.x == 0) g_velred[blockIdx.x] = sm[0];
}

// ------------------- picked logit (packed operands) --------------------------
__global__ void picked_kernel(const float* __restrict__ decB) {
    int r = blockIdx.x*8 + threadIdx.x/32;
    int lane = threadIdx.x % 32;
    if (r >= g_nvalid) return;
    int lab = g_complabel[r];
    float s = 0.f;
    for (int i = lane; i < DD; i += 32) {
        __nv_bfloat16 a = g_habpk[pk(r, i, 8)];
        __nv_bfloat16 w = g_wdecP[pk(lab, i, 8)];
        s += __bfloat162float(a) * __bfloat162float(w);
    }
#pragma unroll
    for (int off = 16; off; off >>= 1) s += __shfl_xor_sync(0xffffffffu, s, off);
    if (lane == 0) g_picked[r] = s + decB[lab];
}

// ------------------- logsumexp combine ---------------------------------------
__global__ void combine_kernel() {
    int r = blockIdx.x;
    int nv = g_nvalid;
    float m = -1e30f, s = 0.f;
    if (r < nv) {
        for (int i = threadIdx.x; i < NCH2; i += blockDim.x) {
            float2 p = g_smpart[(size_t)r*NCH2 + i];
            if (p.x > m) { s = s*expf(m - p.x) + p.y; m = p.x; }
            else         { s += p.y*expf(p.x - m); }
        }
    }
    __shared__ float sm[128], ss[128];
    sm[threadIdx.x] = m; ss[threadIdx.x] = s;
    __syncthreads();
    for (int st = 64; st; st >>= 1) {
        if (threadIdx.x < st) {
            float m1 = sm[threadIdx.x], s1 = ss[threadIdx.x];
            float m2 = sm[threadIdx.x+st], s2 = ss[threadIdx.x+st];
            float M = fmaxf(m1, m2);
            sm[threadIdx.x] = M;
            ss[threadIdx.x] = s1*expf(m1 - M) + s2*expf(m2 - M);
        }
        __syncthreads();
    }
    if (threadIdx.x == 0) {
        if (r < nv) {
            float lse = sm[0] + logf(ss[0]);
            g_rowrecon[r] = lse - g_picked[r];
        } else {
            g_rowrecon[r] = 0.f;
        }
    }
}

// ------------------- final loss ----------------------------------------------
__global__ void final_kernel(float* __restrict__ out) {
    __shared__ float sm[256];
    int tid = threadIdx.x;
    int nv = g_nvalid;
    sm[tid] = g_velred[tid];
    __syncthreads();
    for (int st = 128; st; st >>= 1) { if (tid < st) sm[tid] += sm[tid+st]; __syncthreads(); }
    float vel = sm[0] / ((float)nv * (float)DD);
    __syncthreads();
    float r = 0.f;
    for (int i = tid; i < nv; i += 256) r += g_rowrecon[i];
    sm[tid] = r;
    __syncthreads();
    for (int st = 128; st; st >>= 1) { if (tid < st) sm[tid] += sm[tid+st]; __syncthreads(); }
    if (tid == 0) out[0] = vel + 0.1f * (sm[0] / (float)nv);
}

// ------------------- host side -----------------------------------------------
extern "C" void kernel_launch(void* const* d_in, const int* in_sizes, int n_in,
                              void* d_out, int out_size) {
    (void)in_sizes; (void)n_in; (void)out_size;
    const int*   tok       = (const int*)  d_in[0];
    const int*   motif_ids = (const int*)  d_in[1];
    const int*   motif_len = (const int*)  d_in[2];
    const int*   ws        = (const int*)  d_in[3];
    const int*   we        = (const int*)  d_in[4];
    const float* t         = (const float*)d_in[5];
    const float* x0        = (const float*)d_in[6];
    const float* emb       = (const float*)d_in[7];
    const float* decW      = (const float*)d_in[8];
    const float* decB      = (const float*)d_in[9];
    const float* adW       = (const float*)d_in[10];
    const float* adB       = (const float*)d_in[11];
    const float* tpW       = (const float*)d_in[12];
    const float* tpB       = (const float*)d_in[13];
    const float* cpW       = (const float*)d_in[14];
    const float* cpB       = (const float*)d_in[15];
    const float* qkvW      = (const float*)d_in[16];
    const float* qkvB      = (const float*)d_in[17];
    const float* aoW       = (const float*)d_in[18];
    const float* aoB       = (const float*)d_in[19];
    const float* f1W       = (const float*)d_in[20];
    const float* f1B       = (const float*)d_in[21];
    const float* f2W       = (const float*)d_in[22];
    const float* f2B       = (const float*)d_in[23];
    const float* ln1g      = (const float*)d_in[24];
    const float* ln1b      = (const float*)d_in[25];
    const float* ln2g      = (const float*)d_in[26];
    const float* ln2b      = (const float*)d_in[27];
    const float* outW      = (const float*)d_in[28];
    const float* outB      = (const float*)d_in[29];

    static bool inited = false;
    static float *p_x, *p_tmp, *p_predv, *p_qkv;
    static __nv_bfloat16 *p_xpk, *p_ctxpk, *p_ffpk, *p_px1pk, *p_habpk;
    static __nv_bfloat16 *p_wqkvP, *p_waoP, *p_wf1P, *p_wf2P, *p_woutP, *p_wadP, *p_wdecP;
    if (!inited) {
        cudaGetSymbolAddress((void**)&p_x,      g_x);
        cudaGetSymbolAddress((void**)&p_tmp,    g_tmp);
        cudaGetSymbolAddress((void**)&p_predv,  g_predv);
        cudaGetSymbolAddress((void**)&p_qkv,    g_qkv);
        cudaGetSymbolAddress((void**)&p_xpk,    g_xpk);
        cudaGetSymbolAddress((void**)&p_ctxpk,  g_ctxpk);
        cudaGetSymbolAddress((void**)&p_ffpk,   g_ffpk);
        cudaGetSymbolAddress((void**)&p_px1pk,  g_px1pk);
        cudaGetSymbolAddress((void**)&p_habpk,  g_habpk);
        cudaGetSymbolAddress((void**)&p_wqkvP,  g_wqkvP);
        cudaGetSymbolAddress((void**)&p_waoP,   g_waoP);
        cudaGetSymbolAddress((void**)&p_wf1P,   g_wf1P);
        cudaGetSymbolAddress((void**)&p_wf2P,   g_wf2P);
        cudaGetSymbolAddress((void**)&p_woutP,  g_woutP);
        cudaGetSymbolAddress((void**)&p_wadP,   g_wadP);
        cudaGetSymbolAddress((void**)&p_wdecP,  g_wdecP);
        cudaFuncSetAttribute(gemm64, cudaFuncAttributeMaxDynamicSharedMemorySize, DYNSM);
        cudaFuncSetAttribute(decode64, cudaFuncAttributeMaxDynamicSharedMemorySize, DYNSM);
        cudaFuncSetAttribute(attn_fused, cudaFuncAttributeMaxDynamicSharedMemorySize, ATTSMEM);
        inited = true;
    }

    // 0: weights fp32 -> packed bf16 (one launch, single stream)
    wpack_all<<<12864, 256>>>(qkvW, aoW, f1W, f2W, outW, adW, decW);
    // 1-2: pools + prep
    pool_partial<<<dim3(BB, 8), 512>>>(tok, ws, we, emb);
    prep_kernel<<<BB, 512>>>(motif_ids, motif_len, ws, we, emb, t);
    // 3: temb + cond projections
    gemm_small4<<<1024, 256>>>(tpW, tpB, cpW, cpB);
    // 4: build x (+ cond rows + compaction)
    build_all2<<<4129, 256>>>(tok, ws, we, t, x0, emb);

    // transformer layers
    for (int i = 0; i < NLAYER; i++) {
        gemm64<<<dim3(12, 34), 256, DYNSM>>>(
            p_xpk, p_wqkvP + (size_t)i*12*8*TILE_ELEMS, qkvB + (size_t)i*3*DD,
            p_qkv, (__nv_bfloat16*)0, RT, 3*DD, 8, 0, 0);
        attn_fused<<<BB*HH, 256, ATTSMEM>>>();
        gemm64<<<dim3(4, 34), 256, DYNSM>>>(
            p_ctxpk, p_waoP + (size_t)i*4*8*TILE_ELEMS, aoB + (size_t)i*DD,
            p_tmp, (__nv_bfloat16*)0, RT, DD, 8, 0, 0);
        ln_warp<<<(RT + 7)/8, 256>>>(p_x, p_xpk, p_tmp, ln1g + (size_t)i*DD, ln1b + (size_t)i*DD);
        gemm64<<<dim3(16, 34), 256, DYNSM>>>(
            p_xpk, p_wf1P + (size_t)i*16*8*TILE_ELEMS, f1B + (size_t)i*FF,
            (float*)0, p_ffpk, RT, FF, 8, 0, 1);
        gemm64<<<dim3(4, 34), 256, DYNSM>>>(
            p_ffpk, p_wf2P + (size_t)i*4*32*TILE_ELEMS, f2B + (size_t)i*DD,
            p_tmp, (__nv_bfloat16*)0, RT, DD, 32, 0, 0);
        ln_warp<<<(RT + 7)/8, 256>>>(p_x, p_xpk, p_tmp, ln2g + (size_t)i*DD, ln2b + (size_t)i*DD);
    }

    // pred_v over all transformer rows (valid rows consumed by velpred)
    gemm64<<<dim3(4, 34), 256, DYNSM>>>(
        p_xpk, p_woutP, outB, p_predv, (__nv_bfloat16*)0, RT, DD, 8, 0, 0);
    velpred_kernel<<<256, 256>>>(t, x0);
    // adapter over compact valid rows -> packed hab
    gemm64<<<dim3(4, 32), 256, DYNSM>>>(
        p_px1pk, p_wadP, adB, (float*)0, p_habpk, WR, DD, 8, 1, 0);
    // decode GEMM with fused online softmax partials
    decode64<<<dim3(NCH2, 32), 256, DYNSM>>>(p_habpk, p_wdecP, decB);
    picked_kernel<<<WR/8, 256>>>(decB);
    combine_kernel<<<WR, 128>>>();
    final_kernel<<<1, 256>>>((float*)d_out);
}